// round 15
// baseline (speedup 1.0000x reference)
#include <cuda_runtime.h>
#include <math.h>

#define NS 100000
#define NQUAD (NS / 4)      // 25000 quads of 4 consecutive rows
#define H 128
#define NBLK 740            // 5 blocks/SM * 148 SMs (128-thread blocks, 20 warps/SM)
#define NTHREADS 128
#define WPB 4
#define TOTW (NBLK * WPB)   // 2960 warps

typedef unsigned long long ull;

// Per-block partials: 0:t_mu+ 1:t_mu- 2:t_sig+ 3:t_sig- 4:S+ 5:S-
__device__ float g_part[6][NBLK];
__device__ int g_count = 0;

__device__ __forceinline__ ull ff2(ull a, ull b, ull c) {
    ull r;
    asm("fma.rn.f32x2 %0, %1, %2, %3;" : "=l"(r) : "l"(a), "l"(b), "l"(c));
    return r;
}
__device__ __forceinline__ ull pack2(float lo, float hi) {
    ull r;
    asm("mov.b64 %0, {%1, %2};" : "=l"(r) : "f"(lo), "f"(hi));
    return r;
}
__device__ __forceinline__ float sum2(ull a) {
    float lo, hi;
    asm("mov.b64 {%0, %1}, %2;" : "=f"(lo), "=f"(hi) : "l"(a));
    return lo + hi;
}
__device__ __forceinline__ float d4f(float4 a, float4 b) {
    return a.x * b.x + a.y * b.y + a.z * b.z + a.w * b.w;
}

__global__ __launch_bounds__(NTHREADS, 5) void fp_r15(
    const float* __restrict__ e, const float* __restrict__ q,
    const float* __restrict__ mu_w, const float* __restrict__ sigma_w,
    const float* __restrict__ w_key, const float* __restrict__ w_value,
    const float* __restrict__ mu_b, const float* __restrict__ sigma_b,
    float* __restrict__ out) {
    const int tid = threadIdx.x;
    const int lane = tid & 31;
    const int warp = tid >> 5;
    const int s = lane & 7;      // column slot within 8-lane row group
    const int g = lane >> 3;     // which of the 4 rows in the quad

    // ── one-time fragment: q̂ only. mu/sigma applied in epilogue. ──
    const float4* __restrict__ q4p = reinterpret_cast<const float4*>(q);
    float4 qa = q4p[s], qb = q4p[s + 8], qc = q4p[s + 16], qe = q4p[s + 24];
    float qn = d4f(qa, qa) + d4f(qb, qb) + d4f(qc, qc) + d4f(qe, qe);
    qn += __shfl_xor_sync(0xffffffffu, qn, 1);
    qn += __shfl_xor_sync(0xffffffffu, qn, 2);
    qn += __shfl_xor_sync(0xffffffffu, qn, 4);
    const float rq = rsqrtf(qn);
    ull qf[8];
    qf[0] = pack2(qa.x * rq, qa.y * rq);  qf[1] = pack2(qa.z * rq, qa.w * rq);
    qf[2] = pack2(qb.x * rq, qb.y * rq);  qf[3] = pack2(qb.z * rq, qb.w * rq);
    qf[4] = pack2(qc.x * rq, qc.y * rq);  qf[5] = pack2(qc.z * rq, qc.w * rq);
    qf[6] = pack2(qe.x * rq, qe.y * rq);  qf[7] = pack2(qe.z * rq, qe.w * rq);

    // packed column accumulators: lane's 16 columns, + and - branches
    ull pp2[8], pm2[8];
#pragma unroll
    for (int i = 0; i < 8; i++) { pp2[i] = 0; pm2[i] = 0; }
    float spa = 0.f, sma = 0.f;

    // ── main loop: TWO quads (A,B) per iteration — independent chains ──
    const ulonglong2* __restrict__ e16 = reinterpret_cast<const ulonglong2*>(e);
    const int lo = g * 32 + s;   // offset of this lane's first unit within a quad
    int p = blockIdx.x * WPB + warp;
    for (; p < NQUAD; p += 2 * TOTW) {
        const int pB = p + TOTW;
        const bool vB = pB < NQUAD;
        const int pBc = vB ? pB : p;
        const ulonglong2* rpA = e16 + (size_t)p * 128 + lo;
        const ulonglong2* rpB = e16 + (size_t)pBc * 128 + lo;

        ulonglong2 a0 = rpA[0], a1 = rpA[8], a2 = rpA[16], a3 = rpA[24];
        ulonglong2 b0 = rpB[0], b1 = rpB[8], b2 = rpB[16], b3 = rpB[24];

        ull dA = 0, nA = 0, dB = 0, nB = 0;
        dA = ff2(a0.x, qf[0], dA); nA = ff2(a0.x, a0.x, nA);
        dB = ff2(b0.x, qf[0], dB); nB = ff2(b0.x, b0.x, nB);
        dA = ff2(a0.y, qf[1], dA); nA = ff2(a0.y, a0.y, nA);
        dB = ff2(b0.y, qf[1], dB); nB = ff2(b0.y, b0.y, nB);
        dA = ff2(a1.x, qf[2], dA); nA = ff2(a1.x, a1.x, nA);
        dB = ff2(b1.x, qf[2], dB); nB = ff2(b1.x, b1.x, nB);
        dA = ff2(a1.y, qf[3], dA); nA = ff2(a1.y, a1.y, nA);
        dB = ff2(b1.y, qf[3], dB); nB = ff2(b1.y, b1.y, nB);
        dA = ff2(a2.x, qf[4], dA); nA = ff2(a2.x, a2.x, nA);
        dB = ff2(b2.x, qf[4], dB); nB = ff2(b2.x, b2.x, nB);
        dA = ff2(a2.y, qf[5], dA); nA = ff2(a2.y, a2.y, nA);
        dB = ff2(b2.y, qf[5], dB); nB = ff2(b2.y, b2.y, nB);
        dA = ff2(a3.x, qf[6], dA); nA = ff2(a3.x, a3.x, nA);
        dB = ff2(b3.x, qf[6], dB); nB = ff2(b3.x, b3.x, nB);
        dA = ff2(a3.y, qf[7], dA); nA = ff2(a3.y, a3.y, nA);
        dB = ff2(b3.y, qf[7], dB); nB = ff2(b3.y, b3.y, nB);

        float da = sum2(dA), na = sum2(nA);
        float db = sum2(dB), nb = sum2(nB);
        // interleaved butterflies: 12 SHFLs pipeline through the unit
        da += __shfl_xor_sync(0xffffffffu, da, 1);
        db += __shfl_xor_sync(0xffffffffu, db, 1);
        na += __shfl_xor_sync(0xffffffffu, na, 1);
        nb += __shfl_xor_sync(0xffffffffu, nb, 1);
        da += __shfl_xor_sync(0xffffffffu, da, 2);
        db += __shfl_xor_sync(0xffffffffu, db, 2);
        na += __shfl_xor_sync(0xffffffffu, na, 2);
        nb += __shfl_xor_sync(0xffffffffu, nb, 2);
        da += __shfl_xor_sync(0xffffffffu, da, 4);
        db += __shfl_xor_sync(0xffffffffu, db, 4);
        na += __shfl_xor_sync(0xffffffffu, na, 4);
        nb += __shfl_xor_sync(0xffffffffu, nb, 4);

        float ra = rsqrtf(na);
        float rb = rsqrtf(nb);
        float apA = fmaxf(da, 0.f) * ra, amA = fmaxf(-da, 0.f) * ra;
        float apB = fmaxf(db, 0.f) * rb, amB = fmaxf(-db, 0.f) * rb;
        if (!vB) { apB = 0.f; amB = 0.f; }
        spa += apA + apB;
        sma += amA + amB;
        ull apA2 = pack2(apA, apA), amA2 = pack2(amA, amA);
        ull apB2 = pack2(apB, apB), amB2 = pack2(amB, amB);
        pp2[0] = ff2(apA2, a0.x, pp2[0]);  pm2[0] = ff2(amA2, a0.x, pm2[0]);
        pp2[0] = ff2(apB2, b0.x, pp2[0]);  pm2[0] = ff2(amB2, b0.x, pm2[0]);
        pp2[1] = ff2(apA2, a0.y, pp2[1]);  pm2[1] = ff2(amA2, a0.y, pm2[1]);
        pp2[1] = ff2(apB2, b0.y, pp2[1]);  pm2[1] = ff2(amB2, b0.y, pm2[1]);
        pp2[2] = ff2(apA2, a1.x, pp2[2]);  pm2[2] = ff2(amA2, a1.x, pm2[2]);
        pp2[2] = ff2(apB2, b1.x, pp2[2]);  pm2[2] = ff2(amB2, b1.x, pm2[2]);
        pp2[3] = ff2(apA2, a1.y, pp2[3]);  pm2[3] = ff2(amA2, a1.y, pm2[3]);
        pp2[3] = ff2(apB2, b1.y, pp2[3]);  pm2[3] = ff2(amB2, b1.y, pm2[3]);
        pp2[4] = ff2(apA2, a2.x, pp2[4]);  pm2[4] = ff2(amA2, a2.x, pm2[4]);
        pp2[4] = ff2(apB2, b2.x, pp2[4]);  pm2[4] = ff2(amB2, b2.x, pm2[4]);
        pp2[5] = ff2(apA2, a2.y, pp2[5]);  pm2[5] = ff2(amA2, a2.y, pm2[5]);
        pp2[5] = ff2(apB2, b2.y, pp2[5]);  pm2[5] = ff2(amB2, b2.y, pm2[5]);
        pp2[6] = ff2(apA2, a3.x, pp2[6]);  pm2[6] = ff2(amA2, a3.x, pm2[6]);
        pp2[6] = ff2(apB2, b3.x, pp2[6]);  pm2[6] = ff2(amB2, b3.x, pm2[6]);
        pp2[7] = ff2(apA2, a3.y, pp2[7]);  pm2[7] = ff2(amA2, a3.y, pm2[7]);
        pp2[7] = ff2(apB2, b3.y, pp2[7]);  pm2[7] = ff2(amB2, b3.y, pm2[7]);
    }

    // ── epilogue: load mu/sigma fragments and pre-dot (loop regs dead) ──
    const float4* __restrict__ m4p = reinterpret_cast<const float4*>(mu_w);
    const float4* __restrict__ s4p = reinterpret_cast<const float4*>(sigma_w);
    ull t0 = 0, t1 = 0, t2 = 0, t3 = 0;
#pragma unroll
    for (int k = 0; k < 4; k++) {
        float4 m = m4p[s + 8 * k];
        float4 w = s4p[s + 8 * k];
        ull m0 = pack2(m.x, m.y), m1 = pack2(m.z, m.w);
        ull w0 = pack2(w.x, w.y), w1 = pack2(w.z, w.w);
        t0 = ff2(pp2[2 * k], m0, t0);  t0 = ff2(pp2[2 * k + 1], m1, t0);
        t1 = ff2(pm2[2 * k], m0, t1);  t1 = ff2(pm2[2 * k + 1], m1, t1);
        t2 = ff2(pp2[2 * k], w0, t2);  t2 = ff2(pp2[2 * k + 1], w1, t2);
        t3 = ff2(pm2[2 * k], w0, t3);  t3 = ff2(pm2[2 * k + 1], w1, t3);
    }
    float u0 = sum2(t0), u1 = sum2(t1), u2 = sum2(t2), u3 = sum2(t3);
#pragma unroll
    for (int o = 16; o > 0; o >>= 1) {
        u0 += __shfl_xor_sync(0xffffffffu, u0, o);
        u1 += __shfl_xor_sync(0xffffffffu, u1, o);
        u2 += __shfl_xor_sync(0xffffffffu, u2, o);
        u3 += __shfl_xor_sync(0xffffffffu, u3, o);
        spa += __shfl_xor_sync(0xffffffffu, spa, o);
        sma += __shfl_xor_sync(0xffffffffu, sma, o);
    }

    __shared__ float wsum[WPB][6];
    __shared__ int is_last;
    if (lane == 0) {
        wsum[warp][0] = u0;
        wsum[warp][1] = u1;
        wsum[warp][2] = u2;
        wsum[warp][3] = u3;
        wsum[warp][4] = spa * 0.125f;   // each row's a counted by its 8 lanes
        wsum[warp][5] = sma * 0.125f;
    }
    __syncthreads();
    if (tid < 6) {
        float acc = 0.f;
#pragma unroll
        for (int w = 0; w < WPB; w++) acc += wsum[w][tid];
        g_part[tid][blockIdx.x] = acc;
    }
    __threadfence();
    __syncthreads();
    if (tid == 0)
        is_last = (atomicAdd(&g_count, 1) == NBLK - 1) ? 1 : 0;
    __syncthreads();
    if (!is_last) return;

    // ── last block: final 6-scalar reduce + the 8 outputs ──
    __shared__ float tot[6];
    for (int qq = warp; qq < 6; qq += WPB) {
        float acc = 0.f;
#pragma unroll
        for (int i = 0; i < (NBLK + 31) / 32; i++) {
            int j = lane + i * 32;
            if (j < NBLK) acc += __ldcg(&g_part[qq][j]);
        }
#pragma unroll
        for (int o = 16; o > 0; o >>= 1)
            acc += __shfl_xor_sync(0xffffffffu, acc, o);
        if (lane == 0) tot[qq] = acc;
    }
    __syncthreads();
    if (tid < 4) {
        const float Sp = fmaxf(tot[4], 1e-6f);
        const float Sm = fmaxf(tot[5], 1e-6f);
        float wk = w_key[tid];
        float wv = w_value[tid];
        bool pos = (wk > 0.f);
        float dmu = pos ? (tot[0] / Sp) : (tot[1] / Sm);
        float dsg = pos ? (tot[2] / Sp) : (tot[3] / Sm);
        float mu_z = wv * dmu + mu_b[0];
        float x = wv * dsg + sigma_b[0];
        float sig_z = fmaxf(x, 0.f) + log1pf(expf(-fabsf(x)));
        out[tid] = mu_z;
        out[4 + tid] = sig_z;
    }
    if (tid == 0) g_count = 0;  // reset for next graph replay
}

extern "C" void kernel_launch(void* const* d_in, const int* in_sizes, int n_in,
                              void* d_out, int out_size) {
    const float* e       = (const float*)d_in[0];
    const float* w_key   = (const float*)d_in[1];
    const float* w_value = (const float*)d_in[2];
    const float* q       = (const float*)d_in[3];
    const float* mu_w    = (const float*)d_in[4];
    const float* mu_b    = (const float*)d_in[5];
    const float* sigma_w = (const float*)d_in[6];
    const float* sigma_b = (const float*)d_in[7];
    float* out = (float*)d_out;

    fp_r15<<<NBLK, NTHREADS>>>(e, q, mu_w, sigma_w, w_key, w_value, mu_b, sigma_b, out);
}